// round 7
// baseline (speedup 1.0000x reference)
#include <cuda_runtime.h>
#include <math.h>
#include <stdint.h>

#define N0 4096
#define DIMF 320
#define ALPHA_ 0.2f

// level sizes: 4096 -> 3686 -> 2580 -> 1548 -> 774
#define N1 3686
#define N2 2580
#define N3 1548
#define N4 774
#define W0c 128
#define W1c 116
#define W2c 81
#define W3c 49
#define W4c 25

// ---------------- static device scratch (no runtime allocation) -------------
__device__ uint32_t g_mask0[N0 * W0c];
__device__ uint32_t g_mask1[N1 * W1c];
__device__ uint32_t g_mask2[N2 * W2c];
__device__ uint32_t g_mask3[N3 * W3c];
__device__ uint32_t g_mask4[N4 * W4c];

__device__ float g_featA[N0 * DIMF];
__device__ float g_featB[N0 * DIMF];
__device__ float g_Wh[N0 * DIMF];
__device__ float g_Ct[N0 * DIMF];
__device__ float g_org[N0 * DIMF];
__device__ float g_dn[4 * N0 * DIMF];
__device__ float g_cat[N0 * 2 * DIMF];
__device__ float g_wh1v[N0];
__device__ float g_wh2v[N0];
__device__ float g_vbuf[2 * N0];
__device__ float g_sumsq[32];
__device__ float g_part[512];
__device__ float g_scores[N0];
__device__ float g_valsbuf[4 * N0];
__device__ int   g_idxbuf[4 * N0];

// ---------------- kernels ---------------------------------------------------

// adjacency -> bitmask, coalesced + ballot. grid=N0, block=128 (4 warps)
__global__ void k_build_mask0(const float* __restrict__ A, uint32_t* __restrict__ mask) {
    int i = blockIdx.x;
    int lane = threadIdx.x & 31, warp = threadIdx.x >> 5;
    const float* row = A + (size_t)i * N0;
    for (int base = 0; base < N0; base += 128) {
        int col = base + warp * 32 + lane;
        int bit = row[col] > 0.f;
        uint32_t w = __ballot_sync(0xffffffffu, bit);
        if (lane == 0) mask[(size_t)i * W0c + (base >> 5) + warp] = w;
    }
}

__global__ void k_eig_init(float* __restrict__ v) {
    int i = blockIdx.x * blockDim.x + threadIdx.x;
    if (i < N0) v[i] = 1.0f / (float)N0;
}

// vout = (A @ vin) * (1/(||v_prev||+eps))  -- deferred normalization (exact)
__global__ void k_eig_matvec(const uint32_t* __restrict__ mask, const float* __restrict__ vin,
                             float* __restrict__ vout, const float* __restrict__ sumsq,
                             float* __restrict__ part, int it) {
    int warp = threadIdx.x >> 5, lane = threadIdx.x & 31;
    int row = blockIdx.x * 8 + warp;
    float sprev = 1.0f;
    if (it > 0) sprev = 1.0f / (sqrtf(sumsq[it - 1]) + 1e-12f);
    float acc = 0.f;
    const uint32_t* mrow = mask + (size_t)row * W0c;
    for (int w = lane; w < W0c; w += 32) {
        uint32_t m = mrow[w];
        int base = w * 32;
        while (m) {
            int b = __ffs(m) - 1;
            m &= m - 1;
            acc += vin[base + b];
        }
    }
    for (int o = 16; o; o >>= 1) acc += __shfl_xor_sync(0xffffffffu, acc, o);
    __shared__ float ss[8];
    if (lane == 0) {
        float val = acc * sprev;
        vout[row] = val;
        ss[warp] = val * val;
    }
    __syncthreads();
    if (threadIdx.x == 0) {
        float t = 0.f;
        for (int q = 0; q < 8; q++) t += ss[q];
        part[blockIdx.x] = t;
    }
}

__global__ void k_eig_reduce(const float* __restrict__ part, float* __restrict__ sumsq, int it) {
    __shared__ float sh[512];
    sh[threadIdx.x] = part[threadIdx.x];
    __syncthreads();
    for (int s = 256; s; s >>= 1) {
        if (threadIdx.x < s) sh[threadIdx.x] += sh[threadIdx.x + s];
        __syncthreads();
    }
    if (threadIdx.x == 0) sumsq[it] = sh[0];
}

// Xc = [X, centrality]  (grid=N0, block=320)
__global__ void k_build_xc(const float* __restrict__ X, const float* __restrict__ vraw,
                           const float* __restrict__ sumsq, float* __restrict__ out) {
    int i = blockIdx.x, c = threadIdx.x;
    float val;
    if (c < 319) {
        val = X[(size_t)i * 319 + c];
    } else {
        float s = 1.0f / (sqrtf(sumsq[29]) + 1e-12f);
        val = vraw[i] * s;
    }
    out[(size_t)i * DIMF + c] = val;
}

// C[n,320] = A[n,K] @ B  (B row-major [K,320]) or transB: C = A @ B^T (B [320,K])
// 128x64 tile, 8x4 microtile, BK=16, 256 threads
__global__ void k_gemm(const float* __restrict__ A, const float* __restrict__ B,
                       float* __restrict__ C, int n, int K, int transB) {
    __shared__ float As[16][132];
    __shared__ float Bs[16][68];
    int tid = threadIdx.x;
    int tx = tid & 15, ty = tid >> 4;
    int bm = blockIdx.y << 7, bn = blockIdx.x << 6;
    float acc[8][4];
#pragma unroll
    for (int r = 0; r < 8; r++)
#pragma unroll
        for (int c = 0; c < 4; c++) acc[r][c] = 0.f;
    int lm = tid >> 1, lk8 = (tid & 1) << 3;
    int bkk = tid >> 4, bj4 = (tid & 15) << 2;
    int tbj = tid >> 2, tbk4 = (tid & 3) << 2;
    for (int k0 = 0; k0 < K; k0 += 16) {
        float4 a0 = make_float4(0.f, 0.f, 0.f, 0.f), a1 = a0;
        if (bm + lm < n) {
            const float4* p = reinterpret_cast<const float4*>(A + (size_t)(bm + lm) * K + k0 + lk8);
            a0 = p[0];
            a1 = p[1];
        }
        As[lk8 + 0][lm] = a0.x; As[lk8 + 1][lm] = a0.y; As[lk8 + 2][lm] = a0.z; As[lk8 + 3][lm] = a0.w;
        As[lk8 + 4][lm] = a1.x; As[lk8 + 5][lm] = a1.y; As[lk8 + 6][lm] = a1.z; As[lk8 + 7][lm] = a1.w;
        if (!transB) {
            const float4* p = reinterpret_cast<const float4*>(B + (size_t)(k0 + bkk) * DIMF + bn + bj4);
            float4 b4 = *p;
            Bs[bkk][bj4 + 0] = b4.x; Bs[bkk][bj4 + 1] = b4.y;
            Bs[bkk][bj4 + 2] = b4.z; Bs[bkk][bj4 + 3] = b4.w;
        } else {
            const float4* p = reinterpret_cast<const float4*>(B + (size_t)(bn + tbj) * K + k0 + tbk4);
            float4 b4 = *p;
            Bs[tbk4 + 0][tbj] = b4.x; Bs[tbk4 + 1][tbj] = b4.y;
            Bs[tbk4 + 2][tbj] = b4.z; Bs[tbk4 + 3][tbj] = b4.w;
        }
        __syncthreads();
#pragma unroll
        for (int kk = 0; kk < 16; kk++) {
            float ra[8], rb[4];
#pragma unroll
            for (int r = 0; r < 8; r++) ra[r] = As[kk][(ty << 3) + r];
#pragma unroll
            for (int c = 0; c < 4; c++) rb[c] = Bs[kk][(tx << 2) + c];
#pragma unroll
            for (int r = 0; r < 8; r++)
#pragma unroll
                for (int c = 0; c < 4; c++) acc[r][c] = fmaf(ra[r], rb[c], acc[r][c]);
        }
        __syncthreads();
    }
#pragma unroll
    for (int r = 0; r < 8; r++) {
        int row = bm + (ty << 3) + r;
        if (row < n) {
#pragma unroll
            for (int c = 0; c < 4; c++)
                C[(size_t)row * DIMF + bn + (tx << 2) + c] = acc[r][c];
        }
    }
}

// Wh1 = Wh @ a[:320], Wh2 = Wh @ a[320:]. grid=(n+7)/8, block=256
__global__ void k_wh12(const float* __restrict__ Wh, const float* __restrict__ a,
                       float* __restrict__ wh1, float* __restrict__ wh2, int n) {
    int warp = threadIdx.x >> 5, lane = threadIdx.x & 31;
    int row = blockIdx.x * 8 + warp;
    if (row >= n) return;
    const float* wr = Wh + (size_t)row * DIMF;
    float s1 = 0.f, s2 = 0.f;
#pragma unroll
    for (int u = 0; u < 10; u++) {
        int c = lane + 32 * u;
        float w = wr[c];
        s1 = fmaf(w, a[c], s1);
        s2 = fmaf(w, a[DIMF + c], s2);
    }
    for (int o = 16; o; o >>= 1) {
        s1 += __shfl_xor_sync(0xffffffffu, s1, o);
        s2 += __shfl_xor_sync(0xffffffffu, s2, o);
    }
    if (lane == 0) { wh1[row] = s1; wh2[row] = s2; }
}

// fused masked softmax + sparse aggregation; warp per row. grid=(n+7)/8, block=256
__global__ void k_attn(const float* __restrict__ Wh, const float* __restrict__ wh1,
                       const float* __restrict__ wh2, const uint32_t* __restrict__ mask,
                       int n, int words, float* __restrict__ out,
                       const float* __restrict__ skip, int do_elu) {
    int warp = threadIdx.x >> 5, lane = threadIdx.x & 31;
    int row = blockIdx.x * 8 + warp;
    if (row >= n) return;
    const uint32_t* mrow = mask + (size_t)row * words;
    float wh1i = wh1[row];

    // sweep 1: row max + degree
    float m = -3.4e38f;
    int deg = 0;
    for (int w = lane; w < words; w += 32) {
        uint32_t mm = mrow[w];
        deg += __popc(mm);
        int base = w * 32;
        while (mm) {
            int b = __ffs(mm) - 1;
            mm &= mm - 1;
            float e = wh1i + wh2[base + b];
            e = e > 0.f ? e : ALPHA_ * e;
            m = fmaxf(m, e);
        }
    }
    for (int o = 16; o; o >>= 1) {
        m = fmaxf(m, __shfl_xor_sync(0xffffffffu, m, o));
        deg += __shfl_xor_sync(0xffffffffu, deg, o);
    }

    float accs[10];
#pragma unroll
    for (int u = 0; u < 10; u++) accs[u] = 0.f;

    if (deg > 0) {
        // sweep 2: sum of exp
        float s = 0.f;
        for (int w = lane; w < words; w += 32) {
            uint32_t mm = mrow[w];
            int base = w * 32;
            while (mm) {
                int b = __ffs(mm) - 1;
                mm &= mm - 1;
                float e = wh1i + wh2[base + b];
                e = e > 0.f ? e : ALPHA_ * e;
                s += expf(e - m);
            }
        }
        for (int o = 16; o; o >>= 1) s += __shfl_xor_sync(0xffffffffu, s, o);
        float invs = 1.0f / s;

        // sweep 3: weighted aggregation of Wh rows
        for (int w = 0; w < words; w++) {
            uint32_t word = mrow[w];
            if (!word) continue;
            float p = 0.f;
            if ((word >> lane) & 1u) {
                float e = wh1i + wh2[w * 32 + lane];
                e = e > 0.f ? e : ALPHA_ * e;
                p = expf(e - m);
            }
            uint32_t bb = word;
            while (bb) {
                int src = __ffs(bb) - 1;
                bb &= bb - 1;
                float pj = __shfl_sync(0xffffffffu, p, src);
                const float* whr = Wh + (size_t)(w * 32 + src) * DIMF + lane;
#pragma unroll
                for (int u = 0; u < 10; u++) accs[u] = fmaf(pj, whr[u * 32], accs[u]);
            }
        }
#pragma unroll
        for (int u = 0; u < 10; u++) accs[u] *= invs;
    } else {
        // fully-masked row -> softmax uniform over all n (matches reference NEG fill)
        for (int j = 0; j < n; j++) {
            const float* whr = Wh + (size_t)j * DIMF + lane;
#pragma unroll
            for (int u = 0; u < 10; u++) accs[u] += whr[u * 32];
        }
        float invn = 1.0f / (float)n;
#pragma unroll
        for (int u = 0; u < 10; u++) accs[u] *= invn;
    }

    float* orow = out + (size_t)row * DIMF;
    const float* srow = skip ? (skip + (size_t)row * DIMF) : (const float*)0;
#pragma unroll
    for (int u = 0; u < 10; u++) {
        float v = accs[u];
        if (do_elu) v = v > 0.f ? v : expm1f(v);
        if (srow) v += srow[lane + 32 * u];
        orow[lane + 32 * u] = v;
    }
}

// pool scores: sigmoid((X@w + b)/100). grid=(n+7)/8, block=256
__global__ void k_score(const float* __restrict__ X, const float* __restrict__ w,
                        const float* __restrict__ b, float* __restrict__ sc, int n) {
    int warp = threadIdx.x >> 5, lane = threadIdx.x & 31;
    int row = blockIdx.x * 8 + warp;
    if (row >= n) return;
    const float* xr = X + (size_t)row * DIMF;
    float s = 0.f;
#pragma unroll
    for (int u = 0; u < 10; u++) s = fmaf(xr[lane + 32 * u], w[lane + 32 * u], s);
    for (int o = 16; o; o >>= 1) s += __shfl_xor_sync(0xffffffffu, s, o);
    if (lane == 0) {
        float z = (s + b[0]) * 0.01f;
        sc[row] = 1.0f / (1.0f + expf(-z));
    }
}

__device__ __forceinline__ int block_exscan(int val, int* wsum) {
    int tid = threadIdx.x, lane = tid & 31, wid = tid >> 5;
    __syncthreads();
    int inc = val;
#pragma unroll
    for (int o = 1; o < 32; o <<= 1) {
        int t = __shfl_up_sync(0xffffffffu, inc, o);
        if (lane >= o) inc += t;
    }
    if (lane == 31) wsum[wid] = inc;
    __syncthreads();
    if (wid == 0) {
        int s = wsum[lane];
#pragma unroll
        for (int o = 1; o < 32; o <<= 1) {
            int t = __shfl_up_sync(0xffffffffu, s, o);
            if (lane >= o) s += t;
        }
        wsum[lane] = s;
    }
    __syncthreads();
    int off = wid ? wsum[wid - 1] : 0;
    return off + inc - val;
}

// deterministic top-k: radix select (4x8-bit passes) + stable compaction.
// single block of 1024 threads; n <= 4096. idx_out ascending-index order.
__global__ void k_topk(const float* __restrict__ sc, int n, int k,
                       int* __restrict__ idx_out, float* __restrict__ vals_out) {
    __shared__ unsigned int hist[256];
    __shared__ unsigned int pref_sh;
    __shared__ int rem_sh;
    __shared__ int wsum[32];
    int tid = threadIdx.x;
    unsigned int prefix = 0;
    int remaining = k;
    for (int shift = 24; shift >= 0; shift -= 8) {
        if (tid < 256) hist[tid] = 0;
        __syncthreads();
        unsigned int mh = (shift == 24) ? 0u : (0xFFFFFFFFu << (shift + 8));
        for (int i = tid; i < n; i += 1024) {
            unsigned int u = __float_as_uint(sc[i]);
            if ((u & mh) == (prefix & mh)) atomicAdd(&hist[(u >> shift) & 0xffu], 1u);
        }
        __syncthreads();
        if (tid == 0) {
            int cum = 0, d = 255;
            for (; d >= 0; d--) {
                int h = (int)hist[d];
                if (cum + h >= remaining) break;
                cum += h;
            }
            pref_sh = prefix | ((unsigned)d << shift);
            rem_sh = remaining - cum;
        }
        __syncthreads();
        prefix = pref_sh;
        remaining = rem_sh;
        __syncthreads();
    }
    unsigned int T = prefix;  // k-th largest bits (scores > 0 so uint order == float order)
    int m = remaining;        // how many == T to keep (lowest indices first)

    int gt[4], eq[4];
    int ceq = 0;
#pragma unroll
    for (int q = 0; q < 4; q++) {
        int i = tid * 4 + q;
        int vld = i < n;
        unsigned int u = vld ? __float_as_uint(sc[i]) : 0u;
        gt[q] = vld && (u > T);
        eq[q] = vld && (u == T);
        ceq += eq[q];
    }
    int eqb = block_exscan(ceq, wsum);
    int keep[4];
    int ck = 0, er = eqb;
#pragma unroll
    for (int q = 0; q < 4; q++) {
        keep[q] = gt[q] || (eq[q] && er < m);
        er += eq[q];
        ck += keep[q];
    }
    int pos = block_exscan(ck, wsum);
#pragma unroll
    for (int q = 0; q < 4; q++) {
        if (keep[q]) {
            int i = tid * 4 + q;
            idx_out[pos] = i;
            vals_out[pos] = sc[i];
            pos++;
        }
    }
}

// new_X[r] = X[idx[r]] * vals[r]. grid=k, block=320
__global__ void k_pool_feat(const float* __restrict__ X, const int* __restrict__ idx,
                            const float* __restrict__ vals, float* __restrict__ out) {
    int r = blockIdx.x, c = threadIdx.x;
    out[(size_t)r * DIMF + c] = X[(size_t)idx[r] * DIMF + c] * vals[r];
}

// pooled bitmask: newmask[r] bit j = oldmask[idx[r]] bit idx[j]. grid=nk, block=256
__global__ void k_pool_mask(const uint32_t* __restrict__ om, int owords,
                            const int* __restrict__ idx, int nk, int nwords,
                            uint32_t* __restrict__ nm) {
    int r = blockIdx.x;
    int oi = idx[r];
    const uint32_t* orow = om + (size_t)oi * owords;
    int lane = threadIdx.x & 31, warp = threadIdx.x >> 5;
    for (int w = warp; w < nwords; w += 8) {
        int jn = w * 32 + lane;
        int bit = 0;
        if (jn < nk) {
            int jo = idx[jn];
            bit = (orow[jo >> 5] >> (jo & 31)) & 1;
        }
        uint32_t word = __ballot_sync(0xffffffffu, bit);
        if (lane == 0) nm[(size_t)r * nwords + w] = word;
    }
}

__global__ void k_zero(float* __restrict__ p, int count) {
    int i = blockIdx.x * blockDim.x + threadIdx.x;
    if (i < count) p[i] = 0.f;
}

// out[idx[r]] = Xp[r] * sigmoid(U[r] + b). grid=kp, block=320
__global__ void k_unpool(const float* __restrict__ Xp, const float* __restrict__ U,
                         const float* __restrict__ b, const int* __restrict__ idx,
                         float* __restrict__ out) {
    int r = blockIdx.x, c = threadIdx.x;
    float x = Xp[(size_t)r * DIMF + c];
    float g = 1.0f / (1.0f + expf(-(U[(size_t)r * DIMF + c] + b[c])));
    out[(size_t)idx[r] * DIMF + c] = x * g;
}

// cat = [Ain, Bin] along dim 1. grid=N0, block=320
__global__ void k_concat(const float* __restrict__ Ain, const float* __restrict__ Bin,
                         float* __restrict__ out) {
    int r = blockIdx.x, c = threadIdx.x;
    out[(size_t)r * (2 * DIMF) + c] = Ain[(size_t)r * DIMF + c];
    out[(size_t)r * (2 * DIMF) + DIMF + c] = Bin[(size_t)r * DIMF + c];
}

// ---------------- host orchestration ----------------------------------------

static void gemm(const float* A, const float* B, float* C, int n, int K, int transB) {
    dim3 g(5, (n + 127) / 128);
    k_gemm<<<g, 256>>>(A, B, C, n, K, transB);
}

extern "C" void kernel_launch(void* const* d_in, const int* in_sizes, int n_in,
                              void* d_out, int out_size) {
    (void)in_sizes; (void)n_in;
    const float* A        = (const float*)d_in[0];
    const float* X        = (const float*)d_in[1];
    const float* start_W  = (const float*)d_in[2];
    const float* start_a  = (const float*)d_in[3];
    const float* bottom_W = (const float*)d_in[4];
    const float* bottom_a = (const float*)d_in[5];
    const float* end_W    = (const float*)d_in[6];
    const float* end_a    = (const float*)d_in[7];
    const float* down_W   = (const float*)d_in[8];
    const float* down_a   = (const float*)d_in[9];
    const float* up_W     = (const float*)d_in[10];
    const float* up_a     = (const float*)d_in[11];
    const float* pool_w   = (const float*)d_in[12];
    const float* pool_b   = (const float*)d_in[13];
    const float* unpool_w = (const float*)d_in[14];
    const float* unpool_b = (const float*)d_in[15];

    void* p;
    uint32_t *m0, *m1, *m2, *m3, *m4;
    float *fa, *fb, *wh, *ct, *org, *dn, *cat, *wh1, *wh2, *vb, *ss, *part, *scores, *valb;
    int* idxb;
    cudaGetSymbolAddress(&p, g_mask0); m0 = (uint32_t*)p;
    cudaGetSymbolAddress(&p, g_mask1); m1 = (uint32_t*)p;
    cudaGetSymbolAddress(&p, g_mask2); m2 = (uint32_t*)p;
    cudaGetSymbolAddress(&p, g_mask3); m3 = (uint32_t*)p;
    cudaGetSymbolAddress(&p, g_mask4); m4 = (uint32_t*)p;
    cudaGetSymbolAddress(&p, g_featA); fa = (float*)p;
    cudaGetSymbolAddress(&p, g_featB); fb = (float*)p;
    cudaGetSymbolAddress(&p, g_Wh); wh = (float*)p;
    cudaGetSymbolAddress(&p, g_Ct); ct = (float*)p;
    cudaGetSymbolAddress(&p, g_org); org = (float*)p;
    cudaGetSymbolAddress(&p, g_dn); dn = (float*)p;
    cudaGetSymbolAddress(&p, g_cat); cat = (float*)p;
    cudaGetSymbolAddress(&p, g_wh1v); wh1 = (float*)p;
    cudaGetSymbolAddress(&p, g_wh2v); wh2 = (float*)p;
    cudaGetSymbolAddress(&p, g_vbuf); vb = (float*)p;
    cudaGetSymbolAddress(&p, g_sumsq); ss = (float*)p;
    cudaGetSymbolAddress(&p, g_part); part = (float*)p;
    cudaGetSymbolAddress(&p, g_scores); scores = (float*)p;
    cudaGetSymbolAddress(&p, g_valsbuf); valb = (float*)p;
    cudaGetSymbolAddress(&p, g_idxbuf); idxb = (int*)p;

    const int nl[5] = {N0, N1, N2, N3, N4};
    const int wl[5] = {W0c, W1c, W2c, W3c, W4c};
    uint32_t* masks[5] = {m0, m1, m2, m3, m4};

    // adjacency bitmask
    k_build_mask0<<<N0, 128>>>(A, m0);

    // eigenvector centrality (30 power iterations, deferred normalization)
    k_eig_init<<<(N0 + 255) / 256, 256>>>(vb);
    for (int it = 0; it < 30; ++it) {
        const float* vin = vb + (it & 1) * N0;
        float* vout = vb + ((it + 1) & 1) * N0;
        k_eig_matvec<<<512, 256>>>(m0, vin, vout, ss, part, it);
        k_eig_reduce<<<1, 512>>>(part, ss, it);
    }
    // Xc = [X, centrality] (after 30 iters raw vector lives in vb[0..N0))
    k_build_xc<<<N0, 320>>>(X, vb, ss, fa);

    // start GAT -> org (= start_gat_outs, and down-path input)
    gemm(fa, start_W, wh, N0, 320, 0);
    k_wh12<<<(N0 + 7) / 8, 256>>>(wh, start_a, wh1, wh2, N0);
    k_attn<<<(N0 + 7) / 8, 256>>>(wh, wh1, wh2, m0, N0, W0c, org, (const float*)0, 1);

    // down path
    const float* H = org;
    for (int i = 0; i < 4; i++) {
        float* dni = dn + (size_t)i * N0 * DIMF;
        gemm(H, down_W + (size_t)i * 320 * 320, wh, nl[i], 320, 0);
        k_wh12<<<(nl[i] + 7) / 8, 256>>>(wh, down_a + (size_t)i * 640, wh1, wh2, nl[i]);
        k_attn<<<(nl[i] + 7) / 8, 256>>>(wh, wh1, wh2, masks[i], nl[i], wl[i], dni,
                                         (const float*)0, 1);
        // pool
        k_score<<<(nl[i] + 7) / 8, 256>>>(dni, pool_w + (size_t)i * 320, pool_b + i,
                                          scores, nl[i]);
        k_topk<<<1, 1024>>>(scores, nl[i], nl[i + 1], idxb + i * N0, valb + i * N0);
        k_pool_feat<<<nl[i + 1], 320>>>(dni, idxb + i * N0, valb + i * N0, fa);
        k_pool_mask<<<nl[i + 1], 256>>>(masks[i], wl[i], idxb + i * N0, nl[i + 1],
                                        wl[i + 1], masks[i + 1]);
        H = fa;
    }

    // bottom GAT
    gemm(fa, bottom_W, wh, N4, 320, 0);
    k_wh12<<<(N4 + 7) / 8, 256>>>(wh, bottom_a, wh1, wh2, N4);
    k_attn<<<(N4 + 7) / 8, 256>>>(wh, wh1, wh2, m4, N4, W4c, fb, (const float*)0, 1);
    H = fb;

    // up path
    for (int i = 0; i < 4; i++) {
        int ui = 3 - i;
        int nup = nl[ui];
        int kp = nl[ui + 1];
        const int* idx = idxb + ui * N0;
        // unpool: gated scatter
        gemm(H, unpool_w + (size_t)i * 320 * 320, ct, kp, 320, 1);
        k_zero<<<(nup * DIMF + 255) / 256, 256>>>(fa, nup * DIMF);
        k_unpool<<<kp, 320>>>(H, ct, unpool_b + (size_t)i * 320, idx, fa);
        // GAT + skip(down_outs[ui])
        gemm(fa, up_W + (size_t)i * 320 * 320, wh, nup, 320, 0);
        k_wh12<<<(nup + 7) / 8, 256>>>(wh, up_a + (size_t)i * 640, wh1, wh2, nup);
        k_attn<<<(nup + 7) / 8, 256>>>(wh, wh1, wh2, masks[ui], nup, wl[ui], fb,
                                       dn + (size_t)ui * N0 * DIMF, 1);
        H = fb;
    }

    // end GAT on [Xh, org] -> d_out[0 : N0*DIMF), no elu
    k_concat<<<N0, 320>>>(fb, org, cat);
    gemm(cat, end_W, wh, N0, 640, 0);
    k_wh12<<<(N0 + 7) / 8, 256>>>(wh, end_a, wh1, wh2, N0);
    float* out = (float*)d_out;
    k_attn<<<(N0 + 7) / 8, 256>>>(wh, wh1, wh2, m0, N0, W0c, out, (const float*)0, 0);

    // second output: start_gat_outs
    if (out_size >= 2 * N0 * DIMF) {
        cudaMemcpyAsync(out + (size_t)N0 * DIMF, org, (size_t)N0 * DIMF * sizeof(float),
                        cudaMemcpyDeviceToDevice);
    }
}

// round 8
// speedup vs baseline: 1.1757x; 1.1757x over previous
#include <cuda_runtime.h>
#include <cuda_fp16.h>
#include <math.h>
#include <stdint.h>

#define N0 4096
#define DIMF 320
#define ALPHA_ 0.2f

// level sizes: 4096 -> 3686 -> 2580 -> 1548 -> 774
#define N1 3686
#define N2 2580
#define N3 1548
#define N4 774
#define W0c 128
#define W1c 116
#define W2c 81
#define W3c 49
#define W4c 25

// ---------------- static device scratch (no runtime allocation) -------------
__device__ uint32_t g_mask0[N0 * W0c];
__device__ uint32_t g_mask1[N1 * W1c];
__device__ uint32_t g_mask2[N2 * W2c];
__device__ uint32_t g_mask3[N3 * W3c];
__device__ uint32_t g_mask4[N4 * W4c];

__device__ float  g_featA[N0 * DIMF];
__device__ float  g_featB[N0 * DIMF];
__device__ float  g_Wh[N0 * DIMF];
__device__ __half g_WhH[N0 * DIMF];
__device__ float  g_Ct[N0 * DIMF];
__device__ float  g_org[N0 * DIMF];
__device__ float  g_dn[4 * N0 * DIMF];
__device__ float  g_cat[N0 * 2 * DIMF];
__device__ float  g_wh1v[N0];
__device__ float  g_wh2v[N0];
__device__ float  g_vbuf[2 * N0];
__device__ float  g_sumsq[32];
__device__ float  g_part[1024];
__device__ float  g_scores[N0];
__device__ float  g_valsbuf[4 * N0];
__device__ int    g_idxbuf[4 * N0];

// ---------------- kernels ---------------------------------------------------

// adjacency -> bitmask, coalesced + ballot. grid=N0, block=128 (4 warps)
__global__ void k_build_mask0(const float* __restrict__ A, uint32_t* __restrict__ mask) {
    int i = blockIdx.x;
    int lane = threadIdx.x & 31, warp = threadIdx.x >> 5;
    const float* row = A + (size_t)i * N0;
    for (int base = 0; base < N0; base += 128) {
        int col = base + warp * 32 + lane;
        int bit = row[col] > 0.f;
        uint32_t w = __ballot_sync(0xffffffffu, bit);
        if (lane == 0) mask[(size_t)i * W0c + (base >> 5) + warp] = w;
    }
}

// fused power-iteration step: per-block reduce of previous partials (deferred
// normalization), masked matvec, new partials. grid=512, block=256.
__global__ void k_eig_matvec(const uint32_t* __restrict__ mask, const float* __restrict__ vin,
                             float* __restrict__ vout, const float* __restrict__ partR,
                             float* __restrict__ partW, int it) {
    __shared__ float sred[8];
    __shared__ float s_sprev;
    int tid = threadIdx.x, lane = tid & 31, warp = tid >> 5;
    if (it > 0) {
        float t = partR[tid] + partR[tid + 256];
        for (int o = 16; o; o >>= 1) t += __shfl_xor_sync(0xffffffffu, t, o);
        if (lane == 0) sred[warp] = t;
        __syncthreads();
        if (tid == 0) {
            float tt = 0.f;
            for (int q = 0; q < 8; q++) tt += sred[q];
            s_sprev = 1.0f / (sqrtf(tt) + 1e-12f);
        }
    } else {
        if (tid == 0) s_sprev = 1.0f;
    }
    __syncthreads();
    float sprev = s_sprev;

    int row = blockIdx.x * 8 + warp;
    float acc = 0.f;
    const uint32_t* mrow = mask + (size_t)row * W0c;
    if (it == 0) {
        int d = 0;
        for (int w = lane; w < W0c; w += 32) d += __popc(mrow[w]);
        acc = (float)d * (1.0f / (float)N0);
    } else {
        for (int w = lane; w < W0c; w += 32) {
            uint32_t m = mrow[w];
            int base = w * 32;
            while (m) {
                int b = __ffs(m) - 1;
                m &= m - 1;
                acc += vin[base + b];
            }
        }
    }
    for (int o = 16; o; o >>= 1) acc += __shfl_xor_sync(0xffffffffu, acc, o);
    __syncthreads();  // done with sred phase-1
    if (lane == 0) {
        float val = acc * sprev;
        vout[row] = val;
        sred[warp] = val * val;
    }
    __syncthreads();
    if (tid == 0) {
        float t = 0.f;
        for (int q = 0; q < 8; q++) t += sred[q];
        partW[blockIdx.x] = t;
    }
}

__global__ void k_eig_reduce(const float* __restrict__ part, float* __restrict__ sumsq, int it) {
    __shared__ float sh[512];
    sh[threadIdx.x] = part[threadIdx.x];
    __syncthreads();
    for (int s = 256; s; s >>= 1) {
        if (threadIdx.x < s) sh[threadIdx.x] += sh[threadIdx.x + s];
        __syncthreads();
    }
    if (threadIdx.x == 0) sumsq[it] = sh[0];
}

// Xc = [X, centrality]  (grid=N0, block=320)
__global__ void k_build_xc(const float* __restrict__ X, const float* __restrict__ vraw,
                           const float* __restrict__ sumsq, float* __restrict__ out) {
    int i = blockIdx.x, c = threadIdx.x;
    float val;
    if (c < 319) {
        val = X[(size_t)i * 319 + c];
    } else {
        float s = 1.0f / (sqrtf(sumsq[0]) + 1e-12f);
        val = vraw[i] * s;
    }
    out[(size_t)i * DIMF + c] = val;
}

// C[n,320] = A[n,K] @ B  (B row-major [K,320]) or transB: C = A @ B^T (B [320,K])
// optional fp16 shadow copy Ch for the attention aggregation.
// 128x64 tile, 8x4 microtile, BK=16, 256 threads
__global__ void k_gemm(const float* __restrict__ A, const float* __restrict__ B,
                       float* __restrict__ C, __half* __restrict__ Ch,
                       int n, int K, int transB) {
    __shared__ float As[16][132];
    __shared__ float Bs[16][68];
    int tid = threadIdx.x;
    int tx = tid & 15, ty = tid >> 4;
    int bm = blockIdx.y << 7, bn = blockIdx.x << 6;
    float acc[8][4];
#pragma unroll
    for (int r = 0; r < 8; r++)
#pragma unroll
        for (int c = 0; c < 4; c++) acc[r][c] = 0.f;
    int lm = tid >> 1, lk8 = (tid & 1) << 3;
    int bkk = tid >> 4, bj4 = (tid & 15) << 2;
    int tbj = tid >> 2, tbk4 = (tid & 3) << 2;
    for (int k0 = 0; k0 < K; k0 += 16) {
        float4 a0 = make_float4(0.f, 0.f, 0.f, 0.f), a1 = a0;
        if (bm + lm < n) {
            const float4* p = reinterpret_cast<const float4*>(A + (size_t)(bm + lm) * K + k0 + lk8);
            a0 = p[0];
            a1 = p[1];
        }
        As[lk8 + 0][lm] = a0.x; As[lk8 + 1][lm] = a0.y; As[lk8 + 2][lm] = a0.z; As[lk8 + 3][lm] = a0.w;
        As[lk8 + 4][lm] = a1.x; As[lk8 + 5][lm] = a1.y; As[lk8 + 6][lm] = a1.z; As[lk8 + 7][lm] = a1.w;
        if (!transB) {
            const float4* p = reinterpret_cast<const float4*>(B + (size_t)(k0 + bkk) * DIMF + bn + bj4);
            float4 b4 = *p;
            Bs[bkk][bj4 + 0] = b4.x; Bs[bkk][bj4 + 1] = b4.y;
            Bs[bkk][bj4 + 2] = b4.z; Bs[bkk][bj4 + 3] = b4.w;
        } else {
            const float4* p = reinterpret_cast<const float4*>(B + (size_t)(bn + tbj) * K + k0 + tbk4);
            float4 b4 = *p;
            Bs[tbk4 + 0][tbj] = b4.x; Bs[tbk4 + 1][tbj] = b4.y;
            Bs[tbk4 + 2][tbj] = b4.z; Bs[tbk4 + 3][tbj] = b4.w;
        }
        __syncthreads();
#pragma unroll
        for (int kk = 0; kk < 16; kk++) {
            float ra[8], rb[4];
#pragma unroll
            for (int r = 0; r < 8; r++) ra[r] = As[kk][(ty << 3) + r];
#pragma unroll
            for (int c = 0; c < 4; c++) rb[c] = Bs[kk][(tx << 2) + c];
#pragma unroll
            for (int r = 0; r < 8; r++)
#pragma unroll
                for (int c = 0; c < 4; c++) acc[r][c] = fmaf(ra[r], rb[c], acc[r][c]);
        }
        __syncthreads();
    }
#pragma unroll
    for (int r = 0; r < 8; r++) {
        int row = bm + (ty << 3) + r;
        if (row < n) {
#pragma unroll
            for (int c = 0; c < 4; c++) {
                float v = acc[r][c];
                C[(size_t)row * DIMF + bn + (tx << 2) + c] = v;
                if (Ch) Ch[(size_t)row * DIMF + bn + (tx << 2) + c] = __float2half(v);
            }
        }
    }
}

// Wh1 = Wh @ a[:320], Wh2 = Wh @ a[320:]. grid=(n+7)/8, block=256
__global__ void k_wh12(const float* __restrict__ Wh, const float* __restrict__ a,
                       float* __restrict__ wh1, float* __restrict__ wh2, int n) {
    int warp = threadIdx.x >> 5, lane = threadIdx.x & 31;
    int row = blockIdx.x * 8 + warp;
    if (row >= n) return;
    const float* wr = Wh + (size_t)row * DIMF;
    float s1 = 0.f, s2 = 0.f;
#pragma unroll
    for (int u = 0; u < 10; u++) {
        int c = lane + 32 * u;
        float w = wr[c];
        s1 = fmaf(w, a[c], s1);
        s2 = fmaf(w, a[DIMF + c], s2);
    }
    for (int o = 16; o; o >>= 1) {
        s1 += __shfl_xor_sync(0xffffffffu, s1, o);
        s2 += __shfl_xor_sync(0xffffffffu, s2, o);
    }
    if (lane == 0) { wh1[row] = s1; wh2[row] = s2; }
}

// fused masked softmax + sparse aggregation; warp per row. grid=(n+7)/8, block=256
// Wh rows streamed as fp16 (half2), fp32 accumulate; softmax weights fp32.
// sweep1 exploits monotone leaky-relu: max_j leaky(wh1i+wh2j) = leaky(wh1i+max_j wh2j).
// sum-of-exp fused into the aggregation sweep (scale by 1/s at the end).
__global__ void k_attn(const __half* __restrict__ WhH, const float* __restrict__ wh1,
                       const float* __restrict__ wh2, const uint32_t* __restrict__ mask,
                       int n, int words, float* __restrict__ out,
                       const float* __restrict__ skip, int do_elu) {
    int warp = threadIdx.x >> 5, lane = threadIdx.x & 31;
    int row = blockIdx.x * 8 + warp;
    if (row >= n) return;
    const uint32_t* mrow = mask + (size_t)row * words;
    float wh1i = wh1[row];

    // sweep 1: max over neighbors of wh2 + degree
    float m2 = -3.4e38f;
    int deg = 0;
    for (int w = lane; w < words; w += 32) {
        uint32_t mm = mrow[w];
        deg += __popc(mm);
        int base = w * 32;
        while (mm) {
            int b = __ffs(mm) - 1;
            mm &= mm - 1;
            m2 = fmaxf(m2, wh2[base + b]);
        }
    }
    for (int o = 16; o; o >>= 1) {
        m2 = fmaxf(m2, __shfl_xor_sync(0xffffffffu, m2, o));
        deg += __shfl_xor_sync(0xffffffffu, deg, o);
    }
    float mtop = wh1i + m2;
    float m = mtop > 0.f ? mtop : ALPHA_ * mtop;

    float accx[5], accy[5];
#pragma unroll
    for (int u = 0; u < 5; u++) { accx[u] = 0.f; accy[u] = 0.f; }

    if (deg > 0) {
        float s = 0.f;
        for (int w = 0; w < words; w++) {
            uint32_t word = mrow[w];
            if (!word) continue;
            float p = 0.f;
            if ((word >> lane) & 1u) {
                float e = wh1i + wh2[w * 32 + lane];
                e = e > 0.f ? e : ALPHA_ * e;
                p = __expf(e - m);
                s += p;
            }
            uint32_t bb = word;
            while (bb) {
                int src = __ffs(bb) - 1;
                bb &= bb - 1;
                float pj = __shfl_sync(0xffffffffu, p, src);
                const __half2* whr =
                    reinterpret_cast<const __half2*>(WhH + (size_t)(w * 32 + src) * DIMF) + lane;
#pragma unroll
                for (int u = 0; u < 5; u++) {
                    float2 f = __half22float2(whr[u * 32]);
                    accx[u] = fmaf(pj, f.x, accx[u]);
                    accy[u] = fmaf(pj, f.y, accy[u]);
                }
            }
        }
        for (int o = 16; o; o >>= 1) s += __shfl_xor_sync(0xffffffffu, s, o);
        float invs = 1.0f / s;
#pragma unroll
        for (int u = 0; u < 5; u++) { accx[u] *= invs; accy[u] *= invs; }
    } else {
        // fully-masked row -> softmax uniform over all n (matches reference NEG fill)
        for (int j = 0; j < n; j++) {
            const __half2* whr =
                reinterpret_cast<const __half2*>(WhH + (size_t)j * DIMF) + lane;
#pragma unroll
            for (int u = 0; u < 5; u++) {
                float2 f = __half22float2(whr[u * 32]);
                accx[u] += f.x;
                accy[u] += f.y;
            }
        }
        float invn = 1.0f / (float)n;
#pragma unroll
        for (int u = 0; u < 5; u++) { accx[u] *= invn; accy[u] *= invn; }
    }

    float2* orow = reinterpret_cast<float2*>(out + (size_t)row * DIMF);
    const float2* srow = skip ? reinterpret_cast<const float2*>(skip + (size_t)row * DIMF)
                              : (const float2*)0;
#pragma unroll
    for (int u = 0; u < 5; u++) {
        float vx = accx[u], vy = accy[u];
        if (do_elu) {
            vx = vx > 0.f ? vx : expm1f(vx);
            vy = vy > 0.f ? vy : expm1f(vy);
        }
        if (srow) {
            float2 sk = srow[lane + 32 * u];
            vx += sk.x;
            vy += sk.y;
        }
        float2 v2;
        v2.x = vx;
        v2.y = vy;
        orow[lane + 32 * u] = v2;
    }
}

// pool scores: sigmoid((X@w + b)/100). grid=(n+7)/8, block=256
__global__ void k_score(const float* __restrict__ X, const float* __restrict__ w,
                        const float* __restrict__ b, float* __restrict__ sc, int n) {
    int warp = threadIdx.x >> 5, lane = threadIdx.x & 31;
    int row = blockIdx.x * 8 + warp;
    if (row >= n) return;
    const float* xr = X + (size_t)row * DIMF;
    float s = 0.f;
#pragma unroll
    for (int u = 0; u < 10; u++) s = fmaf(xr[lane + 32 * u], w[lane + 32 * u], s);
    for (int o = 16; o; o >>= 1) s += __shfl_xor_sync(0xffffffffu, s, o);
    if (lane == 0) {
        float z = (s + b[0]) * 0.01f;
        sc[row] = 1.0f / (1.0f + expf(-z));
    }
}

__device__ __forceinline__ int block_exscan(int val, int* wsum) {
    int tid = threadIdx.x, lane = tid & 31, wid = tid >> 5;
    __syncthreads();
    int inc = val;
#pragma unroll
    for (int o = 1; o < 32; o <<= 1) {
        int t = __shfl_up_sync(0xffffffffu, inc, o);
        if (lane >= o) inc += t;
    }
    if (lane == 31) wsum[wid] = inc;
    __syncthreads();
    if (wid == 0) {
        int s = wsum[lane];
#pragma unroll
        for (int o = 1; o < 32; o <<= 1) {
            int t = __shfl_up_sync(0xffffffffu, s, o);
            if (lane >= o) s += t;
        }
        wsum[lane] = s;
    }
    __syncthreads();
    int off = wid ? wsum[wid - 1] : 0;
    return off + inc - val;
}

// deterministic top-k: radix select (4x8-bit passes) + stable compaction.
// single block of 1024 threads; n <= 4096. idx_out ascending-index order.
__global__ void k_topk(const float* __restrict__ sc, int n, int k,
                       int* __restrict__ idx_out, float* __restrict__ vals_out) {
    __shared__ unsigned int hist[256];
    __shared__ unsigned int pref_sh;
    __shared__ int rem_sh;
    __shared__ int wsum[32];
    int tid = threadIdx.x;
    unsigned int prefix = 0;
    int remaining = k;
    for (int shift = 24; shift >= 0; shift -= 8) {
        if (tid < 256) hist[tid] = 0;
        __syncthreads();
        unsigned int mh = (shift == 24) ? 0u : (0xFFFFFFFFu << (shift + 8));
        for (int i = tid; i < n; i += 1024) {
            unsigned int u = __float_as_uint(sc[i]);
            if ((u & mh) == (prefix & mh)) atomicAdd(&hist[(u >> shift) & 0xffu], 1u);
        }
        __syncthreads();
        if (tid == 0) {
            int cum = 0, d = 255;
            for (; d >= 0; d--) {
                int h = (int)hist[d];
                if (cum + h >= remaining) break;
                cum += h;
            }
            pref_sh = prefix | ((unsigned)d << shift);
            rem_sh = remaining - cum;
        }
        __syncthreads();
        prefix = pref_sh;
        remaining = rem_sh;
        __syncthreads();
    }
    unsigned int T = prefix;
    int m = remaining;

    int gt[4], eq[4];
    int ceq = 0;
#pragma unroll
    for (int q = 0; q < 4; q++) {
        int i = tid * 4 + q;
        int vld = i < n;
        unsigned int u = vld ? __float_as_uint(sc[i]) : 0u;
        gt[q] = vld && (u > T);
        eq[q] = vld && (u == T);
        ceq += eq[q];
    }
    int eqb = block_exscan(ceq, wsum);
    int keep[4];
    int ck = 0, er = eqb;
#pragma unroll
    for (int q = 0; q < 4; q++) {
        keep[q] = gt[q] || (eq[q] && er < m);
        er += eq[q];
        ck += keep[q];
    }
    int pos = block_exscan(ck, wsum);
#pragma unroll
    for (int q = 0; q < 4; q++) {
        if (keep[q]) {
            int i = tid * 4 + q;
            idx_out[pos] = i;
            vals_out[pos] = sc[i];
            pos++;
        }
    }
}

// new_X[r] = X[idx[r]] * vals[r]. grid=k, block=320
__global__ void k_pool_feat(const float* __restrict__ X, const int* __restrict__ idx,
                            const float* __restrict__ vals, float* __restrict__ out) {
    int r = blockIdx.x, c = threadIdx.x;
    out[(size_t)r * DIMF + c] = X[(size_t)idx[r] * DIMF + c] * vals[r];
}

// pooled bitmask: newmask[r] bit j = oldmask[idx[r]] bit idx[j]. grid=nk, block=256
__global__ void k_pool_mask(const uint32_t* __restrict__ om, int owords,
                            const int* __restrict__ idx, int nk, int nwords,
                            uint32_t* __restrict__ nm) {
    int r = blockIdx.x;
    int oi = idx[r];
    const uint32_t* orow = om + (size_t)oi * owords;
    int lane = threadIdx.x & 31, warp = threadIdx.x >> 5;
    for (int w = warp; w < nwords; w += 8) {
        int jn = w * 32 + lane;
        int bit = 0;
        if (jn < nk) {
            int jo = idx[jn];
            bit = (orow[jo >> 5] >> (jo & 31)) & 1;
        }
        uint32_t word = __ballot_sync(0xffffffffu, bit);
        if (lane == 0) nm[(size_t)r * nwords + w] = word;
    }
}

__global__ void k_zero(float* __restrict__ p, int count) {
    int i = blockIdx.x * blockDim.x + threadIdx.x;
    if (i < count) p[i] = 0.f;
}

// out[idx[r]] = Xp[r] * sigmoid(U[r] + b). grid=kp, block=320
__global__ void k_unpool(const float* __restrict__ Xp, const float* __restrict__ U,
                         const float* __restrict__ b, const int* __restrict__ idx,
                         float* __restrict__ out) {
    int r = blockIdx.x, c = threadIdx.x;
    float x = Xp[(size_t)r * DIMF + c];
    float g = 1.0f / (1.0f + expf(-(U[(size_t)r * DIMF + c] + b[c])));
    out[(size_t)idx[r] * DIMF + c] = x * g;
}

// cat = [Ain, Bin] along dim 1. grid=N0, block=320
__global__ void k_concat(const float* __restrict__ Ain, const float* __restrict__ Bin,
                         float* __restrict__ out) {
    int r = blockIdx.x, c = threadIdx.x;
    out[(size_t)r * (2 * DIMF) + c] = Ain[(size_t)r * DIMF + c];
    out[(size_t)r * (2 * DIMF) + DIMF + c] = Bin[(size_t)r * DIMF + c];
}

// ---------------- host orchestration ----------------------------------------

static void gemm(const float* A, const float* B, float* C, __half* Ch,
                 int n, int K, int transB) {
    dim3 g(5, (n + 127) / 128);
    k_gemm<<<g, 256>>>(A, B, C, Ch, n, K, transB);
}

extern "C" void kernel_launch(void* const* d_in, const int* in_sizes, int n_in,
                              void* d_out, int out_size) {
    (void)in_sizes; (void)n_in;
    const float* A        = (const float*)d_in[0];
    const float* X        = (const float*)d_in[1];
    const float* start_W  = (const float*)d_in[2];
    const float* start_a  = (const float*)d_in[3];
    const float* bottom_W = (const float*)d_in[4];
    const float* bottom_a = (const float*)d_in[5];
    const float* end_W    = (const float*)d_in[6];
    const float* end_a    = (const float*)d_in[7];
    const float* down_W   = (const float*)d_in[8];
    const float* down_a   = (const float*)d_in[9];
    const float* up_W     = (const float*)d_in[10];
    const float* up_a     = (const float*)d_in[11];
    const float* pool_w   = (const float*)d_in[12];
    const float* pool_b   = (const float*)d_in[13];
    const float* unpool_w = (const float*)d_in[14];
    const float* unpool_b = (const float*)d_in[15];

    void* p;
    uint32_t *m0, *m1, *m2, *m3, *m4;
    float *fa, *fb, *wh, *ct, *org, *dn, *cat, *wh1, *wh2, *vb, *ss, *part, *scores, *valb;
    __half* whh;
    int* idxb;
    cudaGetSymbolAddress(&p, g_mask0); m0 = (uint32_t*)p;
    cudaGetSymbolAddress(&p, g_mask1); m1 = (uint32_t*)p;
    cudaGetSymbolAddress(&p, g_mask2); m2 = (uint32_t*)p;
    cudaGetSymbolAddress(&p, g_mask3); m3 = (uint32_t*)p;
    cudaGetSymbolAddress(&p, g_mask4); m4 = (uint32_t*)p;
    cudaGetSymbolAddress(&p, g_featA); fa = (float*)p;
    cudaGetSymbolAddress(&p, g_featB); fb = (float*)p;
    cudaGetSymbolAddress(&p, g_Wh); wh = (float*)p;
    cudaGetSymbolAddress(&p, g_WhH); whh = (__half*)p;
    cudaGetSymbolAddress(&p, g_Ct); ct = (float*)p;
    cudaGetSymbolAddress(&p, g_org); org = (float*)p;
    cudaGetSymbolAddress(&p, g_dn); dn = (float*)p;
    cudaGetSymbolAddress(&p, g_cat); cat = (float*)p;
    cudaGetSymbolAddress(&p, g_wh1v); wh1 = (float*)p;
    cudaGetSymbolAddress(&p, g_wh2v); wh2 = (float*)p;
    cudaGetSymbolAddress(&p, g_vbuf); vb = (float*)p;
    cudaGetSymbolAddress(&p, g_sumsq); ss = (float*)p;
    cudaGetSymbolAddress(&p, g_part); part = (float*)p;
    cudaGetSymbolAddress(&p, g_scores); scores = (float*)p;
    cudaGetSymbolAddress(&p, g_valsbuf); valb = (float*)p;
    cudaGetSymbolAddress(&p, g_idxbuf); idxb = (int*)p;

    const int nl[5] = {N0, N1, N2, N3, N4};
    const int wl[5] = {W0c, W1c, W2c, W3c, W4c};
    uint32_t* masks[5] = {m0, m1, m2, m3, m4};

    // adjacency bitmask
    k_build_mask0<<<N0, 128>>>(A, m0);

    // eigenvector centrality: 30 fused power-iteration steps (deferred norm,
    // double-buffered partials; init folded into it==0 via popc shortcut)
    for (int it = 0; it < 30; ++it) {
        const float* vin = vb + (it & 1) * N0;
        float* vout = vb + ((it + 1) & 1) * N0;
        const float* pr = part + (((it - 1) & 1) & 1) * 512;
        float* pw = part + (it & 1) * 512;
        k_eig_matvec<<<512, 256>>>(m0, vin, vout, (it > 0) ? (part + ((it - 1) & 1) * 512) : pr,
                                   pw, it);
    }
    // final norm of w_30 (partials of it=29 live in slot 1)
    k_eig_reduce<<<1, 512>>>(part + 512, ss, 0);
    // Xc = [X, centrality] (w_30 lives in vb[0..N0))
    k_build_xc<<<N0, 320>>>(X, vb, ss, fa);

    // start GAT -> org (= start_gat_outs, and down-path input)
    gemm(fa, start_W, wh, whh, N0, 320, 0);
    k_wh12<<<(N0 + 7) / 8, 256>>>(wh, start_a, wh1, wh2, N0);
    k_attn<<<(N0 + 7) / 8, 256>>>(whh, wh1, wh2, m0, N0, W0c, org, (const float*)0, 1);

    // down path
    const float* H = org;
    for (int i = 0; i < 4; i++) {
        float* dni = dn + (size_t)i * N0 * DIMF;
        gemm(H, down_W + (size_t)i * 320 * 320, wh, whh, nl[i], 320, 0);
        k_wh12<<<(nl[i] + 7) / 8, 256>>>(wh, down_a + (size_t)i * 640, wh1, wh2, nl[i]);
        k_attn<<<(nl[i] + 7) / 8, 256>>>(whh, wh1, wh2, masks[i], nl[i], wl[i], dni,
                                         (const float*)0, 1);
        // pool
        k_score<<<(nl[i] + 7) / 8, 256>>>(dni, pool_w + (size_t)i * 320, pool_b + i,
                                          scores, nl[i]);
        k_topk<<<1, 1024>>>(scores, nl[i], nl[i + 1], idxb + i * N0, valb + i * N0);
        k_pool_feat<<<nl[i + 1], 320>>>(dni, idxb + i * N0, valb + i * N0, fa);
        k_pool_mask<<<nl[i + 1], 256>>>(masks[i], wl[i], idxb + i * N0, nl[i + 1],
                                        wl[i + 1], masks[i + 1]);
        H = fa;
    }

    // bottom GAT
    gemm(fa, bottom_W, wh, whh, N4, 320, 0);
    k_wh12<<<(N4 + 7) / 8, 256>>>(wh, bottom_a, wh1, wh2, N4);
    k_attn<<<(N4 + 7) / 8, 256>>>(whh, wh1, wh2, m4, N4, W4c, fb, (const float*)0, 1);
    H = fb;

    // up path
    for (int i = 0; i < 4; i++) {
        int ui = 3 - i;
        int nup = nl[ui];
        int kp = nl[ui + 1];
        const int* idx = idxb + ui * N0;
        // unpool: gated scatter
        gemm(H, unpool_w + (size_t)i * 320 * 320, ct, (__half*)0, kp, 320, 1);
        k_zero<<<(nup * DIMF + 255) / 256, 256>>>(fa, nup * DIMF);
        k_unpool<<<kp, 320>>>(H, ct, unpool_b + (size_t)i * 320, idx, fa);
        // GAT + skip(down_outs[ui])
        gemm(fa, up_W + (size_t)i * 320 * 320, wh, whh, nup, 320, 0);
        k_wh12<<<(nup + 7) / 8, 256>>>(wh, up_a + (size_t)i * 640, wh1, wh2, nup);
        k_attn<<<(nup + 7) / 8, 256>>>(whh, wh1, wh2, masks[ui], nup, wl[ui], fb,
                                       dn + (size_t)ui * N0 * DIMF, 1);
        H = fb;
    }

    // end GAT on [Xh, org] -> d_out[0 : N0*DIMF), no elu
    k_concat<<<N0, 320>>>(fb, org, cat);
    gemm(cat, end_W, wh, whh, N0, 640, 0);
    k_wh12<<<(N0 + 7) / 8, 256>>>(wh, end_a, wh1, wh2, N0);
    float* out = (float*)d_out;
    k_attn<<<(N0 + 7) / 8, 256>>>(whh, wh1, wh2, m0, N0, W0c, out, (const float*)0, 0);

    // second output: start_gat_outs
    if (out_size >= 2 * N0 * DIMF) {
        cudaMemcpyAsync(out + (size_t)N0 * DIMF, org, (size_t)N0 * DIMF * sizeof(float),
                        cudaMemcpyDeviceToDevice);
    }
}